// round 1
// baseline (speedup 1.0000x reference)
#include <cuda_runtime.h>
#include <math.h>

#define B_  4
#define H_  8
#define D_  512
#define HD_ 64
#define NQ_ 512
#define NK_ 4096

// Scratch (allocation-free rule: __device__ globals)
__device__ float g_Q[(size_t)B_ * H_ * NQ_ * HD_];    // [B,H,NQ,HD]
__device__ float g_K[(size_t)B_ * H_ * NK_ * HD_];    // [B,H,NK,HD]
__device__ float g_V[(size_t)B_ * H_ * NK_ * HD_];    // [B,H,NK,HD]
__device__ float g_ctx[(size_t)B_ * NQ_ * D_];        // [B,NQ,D]

// ---------------------------------------------------------------------------
// Projection GEMM: Y = X @ W^T + bias
//   X: [M, 512] row-major, W: [512, 512] row-major (row n = output feature n)
//   SPLIT=true  -> Y written as [B, H, N_seq, 64]
//   SPLIT=false -> Y written as [M, 512]
// Tiling: 128x128 block tile, BK=16, 256 threads, 8x8 per thread.
// ---------------------------------------------------------------------------
template <bool SPLIT>
__global__ __launch_bounds__(256) void proj_kernel(
    const float* __restrict__ X, const float* __restrict__ W,
    const float* __restrict__ bias, float* __restrict__ Y, int N_seq)
{
    __shared__ float Xs[16][132];   // [k][m], pad to keep 16B alignment, avoid conflicts
    __shared__ float Ws[16][132];   // [k][n]

    const int tid = threadIdx.x;
    const int bm = blockIdx.x * 128;
    const int bn = blockIdx.y * 128;
    const int tx = tid & 15;        // n direction
    const int ty = tid >> 4;        // m direction

    float acc[8][8];
#pragma unroll
    for (int i = 0; i < 8; i++)
#pragma unroll
        for (int j = 0; j < 8; j++) acc[i][j] = 0.0f;

    for (int k0 = 0; k0 < D_; k0 += 16) {
#pragma unroll
        for (int l = 0; l < 2; l++) {
            int idx = tid * 2 + l;          // 0..511
            int row = idx >> 2;             // 0..127
            int c4  = (idx & 3) << 2;       // 0,4,8,12
            float4 vx = *reinterpret_cast<const float4*>(
                &X[(size_t)(bm + row) * D_ + k0 + c4]);
            Xs[c4 + 0][row] = vx.x; Xs[c4 + 1][row] = vx.y;
            Xs[c4 + 2][row] = vx.z; Xs[c4 + 3][row] = vx.w;
            float4 vw = *reinterpret_cast<const float4*>(
                &W[(size_t)(bn + row) * D_ + k0 + c4]);
            Ws[c4 + 0][row] = vw.x; Ws[c4 + 1][row] = vw.y;
            Ws[c4 + 2][row] = vw.z; Ws[c4 + 3][row] = vw.w;
        }
        __syncthreads();
#pragma unroll
        for (int kk = 0; kk < 16; kk++) {
            float a[8], b[8];
            *reinterpret_cast<float4*>(&a[0]) =
                *reinterpret_cast<const float4*>(&Xs[kk][ty * 8]);
            *reinterpret_cast<float4*>(&a[4]) =
                *reinterpret_cast<const float4*>(&Xs[kk][ty * 8 + 4]);
            *reinterpret_cast<float4*>(&b[0]) =
                *reinterpret_cast<const float4*>(&Ws[kk][tx * 8]);
            *reinterpret_cast<float4*>(&b[4]) =
                *reinterpret_cast<const float4*>(&Ws[kk][tx * 8 + 4]);
#pragma unroll
            for (int i = 0; i < 8; i++)
#pragma unroll
                for (int j = 0; j < 8; j++)
                    acc[i][j] = fmaf(a[i], b[j], acc[i][j]);
        }
        __syncthreads();
    }

#pragma unroll
    for (int i = 0; i < 8; i++) {
        int m = bm + ty * 8 + i;
#pragma unroll
        for (int j = 0; j < 8; j++) {
            int n = bn + tx * 8 + j;
            float val = acc[i][j] + bias[n];
            if (SPLIT) {
                int b  = m / N_seq;
                int s  = m - b * N_seq;
                int h  = n >> 6;
                int hd = n & 63;
                Y[((((size_t)b * H_ + h) * N_seq + s) << 6) + hd] = val;
            } else {
                Y[(size_t)m * D_ + n] = val;
            }
        }
    }
}

// ---------------------------------------------------------------------------
// Fused attention per (b,h, 64 q-rows):
//   Pass 1: S = Q K^T / 8 tile-by-tile (64x64), write RAW scores to A region,
//           maintain online row-max m and row-sum l in registers.
//   Pass 2: re-read raw scores (L2 hot, same thread wrote them), normalize,
//           overwrite A with softmax, accumulate ctx = A @ V.
// 256 threads, 4x4 per thread; row group = 16 tx lanes (shfl_xor reductions).
// ---------------------------------------------------------------------------
__global__ __launch_bounds__(256) void attn_kernel(float* __restrict__ A_out)
{
    __shared__ float Qs[64][65];    // phase 1: Q tile;  phase 2: normalized A tile
    __shared__ float KVs[64][65];   // phase 1: K tile;  phase 2: V tile

    const int tid = threadIdx.x;
    const int tx = tid & 15;
    const int ty = tid >> 4;
    const int bh = blockIdx.x >> 3;     // 0..31 = b*H + h
    const int qt = blockIdx.x & 7;      // q tile (64 rows each)

    const float* __restrict__ Qh = g_Q + (size_t)bh * NQ_ * HD_ + (size_t)qt * 64 * HD_;
    const float* __restrict__ Kh = g_K + (size_t)bh * NK_ * HD_;
    const float* __restrict__ Vh = g_V + (size_t)bh * NK_ * HD_;
    float* __restrict__ Ab = A_out + (size_t)bh * NQ_ * NK_ + (size_t)qt * 64 * NK_;

    // load Q tile [64 x 64]
#pragma unroll
    for (int l = 0; l < 16; l++) {
        int idx = tid + l * 256;
        int r = idx >> 6, c = idx & 63;
        Qs[r][c] = Qh[(size_t)r * HD_ + c];
    }

    float m_run[4], l_run[4];
#pragma unroll
    for (int i = 0; i < 4; i++) { m_run[i] = -1e30f; l_run[i] = 0.0f; }

    // ---------------- Pass 1 ----------------
    for (int kt = 0; kt < 64; kt++) {
        __syncthreads();
#pragma unroll
        for (int l = 0; l < 16; l++) {
            int idx = tid + l * 256;
            int r = idx >> 6, c = idx & 63;
            KVs[r][c] = Kh[((size_t)kt * 64 + r) * HD_ + c];
        }
        __syncthreads();

        float s[4][4];
#pragma unroll
        for (int i = 0; i < 4; i++)
#pragma unroll
            for (int j = 0; j < 4; j++) s[i][j] = 0.0f;

#pragma unroll 16
        for (int kk = 0; kk < 64; kk++) {
            float a[4], b[4];
#pragma unroll
            for (int i = 0; i < 4; i++) a[i] = Qs[ty * 4 + i][kk];
#pragma unroll
            for (int j = 0; j < 4; j++) b[j] = KVs[tx * 4 + j][kk];
#pragma unroll
            for (int i = 0; i < 4; i++)
#pragma unroll
                for (int j = 0; j < 4; j++)
                    s[i][j] = fmaf(a[i], b[j], s[i][j]);
        }

#pragma unroll
        for (int i = 0; i < 4; i++) {
#pragma unroll
            for (int j = 0; j < 4; j++) s[i][j] *= 0.125f;

            // write raw scores (float4, all offsets 16B aligned)
            float4 raw = make_float4(s[i][0], s[i][1], s[i][2], s[i][3]);
            *reinterpret_cast<float4*>(
                &Ab[(size_t)(ty * 4 + i) * NK_ + kt * 64 + tx * 4]) = raw;

            // row reduction across the 16 tx lanes (lane bits 0..3)
            float mx = fmaxf(fmaxf(s[i][0], s[i][1]), fmaxf(s[i][2], s[i][3]));
#pragma unroll
            for (int off = 8; off; off >>= 1)
                mx = fmaxf(mx, __shfl_xor_sync(0xffffffffu, mx, off));
            float se = __expf(s[i][0] - mx) + __expf(s[i][1] - mx) +
                       __expf(s[i][2] - mx) + __expf(s[i][3] - mx);
#pragma unroll
            for (int off = 8; off; off >>= 1)
                se += __shfl_xor_sync(0xffffffffu, se, off);

            float mn = fmaxf(m_run[i], mx);
            l_run[i] = l_run[i] * __expf(m_run[i] - mn) + se * __expf(mx - mn);
            m_run[i] = mn;
        }
    }

    // ---------------- Pass 2 ----------------
    float ctxa[4][4];
#pragma unroll
    for (int i = 0; i < 4; i++)
#pragma unroll
        for (int j = 0; j < 4; j++) ctxa[i][j] = 0.0f;

    float linv[4];
#pragma unroll
    for (int i = 0; i < 4; i++) linv[i] = 1.0f / l_run[i];

    for (int kt = 0; kt < 64; kt++) {
        __syncthreads();
        // load V tile
#pragma unroll
        for (int l = 0; l < 16; l++) {
            int idx = tid + l * 256;
            int r = idx >> 6, c = idx & 63;
            KVs[r][c] = Vh[((size_t)kt * 64 + r) * HD_ + c];
        }
        // normalize this thread's own raw 4x4 (it wrote these itself)
#pragma unroll
        for (int i = 0; i < 4; i++) {
            float* p = &Ab[(size_t)(ty * 4 + i) * NK_ + kt * 64 + tx * 4];
            float4 r4 = *reinterpret_cast<const float4*>(p);
            float4 a4;
            a4.x = __expf(r4.x - m_run[i]) * linv[i];
            a4.y = __expf(r4.y - m_run[i]) * linv[i];
            a4.z = __expf(r4.z - m_run[i]) * linv[i];
            a4.w = __expf(r4.w - m_run[i]) * linv[i];
            *reinterpret_cast<float4*>(p) = a4;
            Qs[ty * 4 + i][tx * 4 + 0] = a4.x;
            Qs[ty * 4 + i][tx * 4 + 1] = a4.y;
            Qs[ty * 4 + i][tx * 4 + 2] = a4.z;
            Qs[ty * 4 + i][tx * 4 + 3] = a4.w;
        }
        __syncthreads();

        // ctx += A_tile(64x64) @ V_tile(64x64)
#pragma unroll 16
        for (int kk = 0; kk < 64; kk++) {
            float a[4], v[4];
#pragma unroll
            for (int i = 0; i < 4; i++) a[i] = Qs[ty * 4 + i][kk];
#pragma unroll
            for (int j = 0; j < 4; j++) v[j] = KVs[kk][tx * 4 + j];
#pragma unroll
            for (int i = 0; i < 4; i++)
#pragma unroll
                for (int j = 0; j < 4; j++)
                    ctxa[i][j] = fmaf(a[i], v[j], ctxa[i][j]);
        }
    }

    // write ctx -> g_ctx[b][q][h*64 + hd]
    const int b0 = bh >> 3;
    const int h  = bh & 7;
#pragma unroll
    for (int i = 0; i < 4; i++) {
        size_t q = (size_t)qt * 64 + ty * 4 + i;
        float4 c4 = make_float4(ctxa[i][0], ctxa[i][1], ctxa[i][2], ctxa[i][3]);
        *reinterpret_cast<float4*>(
            &g_ctx[((size_t)b0 * NQ_ + q) * D_ + h * 64 + tx * 4]) = c4;
    }
}

// ---------------------------------------------------------------------------
extern "C" void kernel_launch(void* const* d_in, const int* in_sizes, int n_in,
                              void* d_out, int out_size)
{
    const float* q  = (const float*)d_in[0];
    const float* k  = (const float*)d_in[1];
    const float* v  = (const float*)d_in[2];
    const float* Wq = (const float*)d_in[3];
    const float* bq = (const float*)d_in[4];
    const float* Wk = (const float*)d_in[5];
    const float* bk = (const float*)d_in[6];
    const float* Wv = (const float*)d_in[7];
    const float* bv = (const float*)d_in[8];
    const float* Wo = (const float*)d_in[9];
    const float* bo = (const float*)d_in[10];

    float* out = (float*)d_out;                         // [B, NQ, D]
    float* A   = out + (size_t)B_ * NQ_ * D_;           // [B, H, NQ, NK]

    float *gQ, *gK, *gV, *gctx;
    cudaGetSymbolAddress((void**)&gQ,  g_Q);
    cudaGetSymbolAddress((void**)&gK,  g_K);
    cudaGetSymbolAddress((void**)&gV,  g_V);
    cudaGetSymbolAddress((void**)&gctx, g_ctx);

    dim3 blk(256);
    // Q projection: M = B*NQ = 2048
    proj_kernel<true><<<dim3(16, 4), blk>>>(q, Wq, bq, gQ, NQ_);
    // K projection: M = B*NK = 16384
    proj_kernel<true><<<dim3(128, 4), blk>>>(k, Wk, bk, gK, NK_);
    // V projection
    proj_kernel<true><<<dim3(128, 4), blk>>>(v, Wv, bv, gV, NK_);
    // attention + softmax (writes A) + ctx
    attn_kernel<<<256, blk>>>(A);
    // output projection: M = 2048
    proj_kernel<false><<<dim3(16, 4), blk>>>(gctx, Wo, bo, out, NQ_);
}

// round 2
// speedup vs baseline: 2.1351x; 2.1351x over previous
#include <cuda_runtime.h>
#include <math.h>

#define B_  4
#define H_  8
#define D_  512
#define HD_ 64
#define NQ_ 512
#define NK_ 4096

// ---------------- scratch (no-alloc rule) ----------------
__device__ float g_Q[(size_t)B_ * H_ * NQ_ * HD_];    // [B,H,NQ,HD]
__device__ float g_K[(size_t)B_ * H_ * NK_ * HD_];    // [B,H,NK,HD]
__device__ float g_V[(size_t)B_ * H_ * NK_ * HD_];    // [B,H,NK,HD]
__device__ float g_ctx[(size_t)B_ * NQ_ * D_];        // [B,NQ,D]

// ---------------- helpers ----------------
__device__ __forceinline__ unsigned f2tf32(float x) {
    unsigned r;
    asm("cvt.rna.tf32.f32 %0, %1;" : "=r"(r) : "f"(x));
    return r;
}

__device__ __forceinline__ void mma_tf32(float* d, const unsigned* a,
                                         const unsigned* b) {
    asm volatile(
        "mma.sync.aligned.m16n8k8.row.col.f32.tf32.tf32.f32 "
        "{%0,%1,%2,%3}, {%4,%5,%6,%7}, {%8,%9}, {%0,%1,%2,%3};"
        : "+f"(d[0]), "+f"(d[1]), "+f"(d[2]), "+f"(d[3])
        : "r"(a[0]), "r"(a[1]), "r"(a[2]), "r"(a[3]),
          "r"(b[0]), "r"(b[1]));
}

// ---------------------------------------------------------------------------
// TF32 projection GEMM: Y = X @ W^T + bias
//   X: [M, 512] row-major, W: [512, 512] row-major (Y[m,n] = sum_k X[m,k] W[n,k])
// Blocktile 128x128, BK=32, 8 warps (2x4), warp tile 64x32.
// Smem stride 36 (== 4 mod 32): conflict-free a-frag (4r+k) and b-frag (4n+k).
// ---------------------------------------------------------------------------
template <bool SPLIT>
__global__ __launch_bounds__(256, 2) void proj_tc(
    const float* __restrict__ X, const float* __restrict__ W,
    const float* __restrict__ bias, float* __restrict__ Y, int N_seq)
{
    __shared__ unsigned Xs[128 * 36];
    __shared__ unsigned Ws[128 * 36];

    const int tid  = threadIdx.x;
    const int lane = tid & 31;
    const int w    = tid >> 5;
    const int wm   = w >> 2;       // 0..1
    const int wn   = w & 3;        // 0..3
    const int g    = lane >> 2;    // 0..7
    const int t    = lane & 3;     // 0..3
    const int bm   = blockIdx.x * 128;
    const int bn   = blockIdx.y * 128;

    float acc[4][4][4];
#pragma unroll
    for (int mi = 0; mi < 4; mi++)
#pragma unroll
        for (int nj = 0; nj < 4; nj++)
#pragma unroll
            for (int rr = 0; rr < 4; rr++) acc[mi][nj][rr] = 0.0f;

    for (int k0 = 0; k0 < D_; k0 += 32) {
        __syncthreads();
        // load X tile 128x32 and W tile 128x32 (convert to tf32 bits)
#pragma unroll
        for (int it = 0; it < 4; it++) {
            int i = it * 256 + tid;            // 0..1023 float4 slots
            int r = i >> 3, c = (i & 7) * 4;
            float4 vx = *reinterpret_cast<const float4*>(
                &X[(size_t)(bm + r) * D_ + k0 + c]);
            uint4 ux = make_uint4(f2tf32(vx.x), f2tf32(vx.y), f2tf32(vx.z), f2tf32(vx.w));
            *reinterpret_cast<uint4*>(&Xs[r * 36 + c]) = ux;
            float4 vw = *reinterpret_cast<const float4*>(
                &W[(size_t)(bn + r) * D_ + k0 + c]);
            uint4 uw = make_uint4(f2tf32(vw.x), f2tf32(vw.y), f2tf32(vw.z), f2tf32(vw.w));
            *reinterpret_cast<uint4*>(&Ws[r * 36 + c]) = uw;
        }
        __syncthreads();

#pragma unroll
        for (int k8 = 0; k8 < 4; k8++) {
            unsigned a[4][4], b[4][2];
            int kk = k8 * 8 + t;
#pragma unroll
            for (int mi = 0; mi < 4; mi++) {
                int r = wm * 64 + mi * 16 + g;
                a[mi][0] = Xs[r * 36 + kk];
                a[mi][1] = Xs[(r + 8) * 36 + kk];
                a[mi][2] = Xs[r * 36 + kk + 4];
                a[mi][3] = Xs[(r + 8) * 36 + kk + 4];
            }
#pragma unroll
            for (int nj = 0; nj < 4; nj++) {
                int n = wn * 32 + nj * 8 + g;
                b[nj][0] = Ws[n * 36 + kk];
                b[nj][1] = Ws[n * 36 + kk + 4];
            }
#pragma unroll
            for (int mi = 0; mi < 4; mi++)
#pragma unroll
                for (int nj = 0; nj < 4; nj++)
                    mma_tf32(acc[mi][nj], a[mi], b[nj]);
        }
    }

    // epilogue
#pragma unroll
    for (int mi = 0; mi < 4; mi++) {
#pragma unroll
        for (int nj = 0; nj < 4; nj++) {
            int n = bn + wn * 32 + nj * 8 + t * 2;
            float b0 = bias[n], b1 = bias[n + 1];
#pragma unroll
            for (int rr = 0; rr < 2; rr++) {
                int m = bm + wm * 64 + mi * 16 + g + rr * 8;
                float2 v = make_float2(acc[mi][nj][rr * 2] + b0,
                                       acc[mi][nj][rr * 2 + 1] + b1);
                if (SPLIT) {
                    int bb = m / N_seq;
                    int s  = m - bb * N_seq;
                    int h  = n >> 6;
                    int hd = n & 63;
                    *reinterpret_cast<float2*>(
                        &Y[((((size_t)bb * H_ + h) * N_seq + s) << 6) + hd]) = v;
                } else {
                    *reinterpret_cast<float2*>(&Y[(size_t)m * D_ + n]) = v;
                }
            }
        }
    }
}

// ---------------------------------------------------------------------------
// TF32 fused attention. One CTA = one (b,h) x 128 q-rows. 256 threads, 8 warps.
// Pass1: S = Q K^T / 8 per 128-wide ktile via mma; raw -> A gmem; online (m,l).
// Pass2: re-read raw, softmax-normalize, final A; stage tf32 in smem; ctx += A V.
// ---------------------------------------------------------------------------
#define STRQ 68     // 64+4  (== 4 mod 32)
#define STRK 68     // pass1 K tile stride (row = kpos): (4n + d) conflict-free
#define STRV 72     // pass2 V tile stride (row = k):    (8k + n) conflict-free
#define STRA 132    // 128+4 (== 4 mod 32)

#define OFF_KV   16896      // floats: after A_sm (128*132); Q_sm overlaps A_sm
#define OFF_REDM 26112
#define OFF_REDL 26624
#define OFF_MRUN 27136
#define OFF_LRUN 27264
#define SMEM_FLOATS 27392   // 109568 bytes

__global__ __launch_bounds__(256, 1) void attn_tc(
    const float* __restrict__ gQ, const float* __restrict__ gK,
    const float* __restrict__ gV, float* __restrict__ A_out,
    float* __restrict__ gctx)
{
    extern __shared__ float sm[];
    float*    Asm  = sm;                       // pass2 A tile (tf32 bits)
    unsigned* Qsm  = (unsigned*)sm;            // pass1 Q tile (tf32 bits), overlaps Asm
    unsigned* KVsm = (unsigned*)(sm + OFF_KV);
    float*    redm = sm + OFF_REDM;
    float*    redl = sm + OFF_REDL;
    float*    mrun = sm + OFF_MRUN;
    float*    lrun = sm + OFF_LRUN;

    const int tid  = threadIdx.x;
    const int lane = tid & 31;
    const int w    = tid >> 5;
    const int g    = lane >> 2;    // 0..7
    const int t    = lane & 3;     // 0..3
    const int bh   = blockIdx.x >> 2;    // 0..31
    const int qt   = blockIdx.x & 3;     // 0..3

    const float* Qg = gQ + ((size_t)bh * NQ_ + qt * 128) * HD_;
    const float* Kg = gK + (size_t)bh * NK_ * HD_;
    const float* Vg = gV + (size_t)bh * NK_ * HD_;
    float* Ab = A_out + ((size_t)bh * NQ_ + qt * 128) * NK_;

    // load Q tile 128x64 (tf32 bits), stride 68
#pragma unroll
    for (int it = 0; it < 8; it++) {
        int i = it * 256 + tid;           // 2048 float4 slots
        int r = i >> 4, c = (i & 15) * 4;
        float4 v = *reinterpret_cast<const float4*>(&Qg[(size_t)r * HD_ + c]);
        uint4 u = make_uint4(f2tf32(v.x), f2tf32(v.y), f2tf32(v.z), f2tf32(v.w));
        *reinterpret_cast<uint4*>(&Qsm[r * STRQ + c]) = u;
    }
    if (tid < 128) { mrun[tid] = -1e30f; lrun[tid] = 0.0f; }

    // prefetch K tile 0
    float4 pre[8];
#pragma unroll
    for (int it = 0; it < 8; it++) {
        int i = it * 256 + tid;
        int r = i >> 4, c = (i & 15) * 4;
        pre[it] = *reinterpret_cast<const float4*>(&Kg[(size_t)r * HD_ + c]);
    }

    // ================= PASS 1 =================
    const int wm = w >> 2;   // 0..1
    const int wn = w & 3;    // 0..3

    for (int kt = 0; kt < 32; kt++) {
        __syncthreads();
        // STS K tile (convert)
#pragma unroll
        for (int it = 0; it < 8; it++) {
            int i = it * 256 + tid;
            int r = i >> 4, c = (i & 15) * 4;
            uint4 u = make_uint4(f2tf32(pre[it].x), f2tf32(pre[it].y),
                                 f2tf32(pre[it].z), f2tf32(pre[it].w));
            *reinterpret_cast<uint4*>(&KVsm[r * STRK + c]) = u;
        }
        if (kt + 1 < 32) {
            const float* Kt = Kg + (size_t)(kt + 1) * 128 * HD_;
#pragma unroll
            for (int it = 0; it < 8; it++) {
                int i = it * 256 + tid;
                int r = i >> 4, c = (i & 15) * 4;
                pre[it] = *reinterpret_cast<const float4*>(&Kt[(size_t)r * HD_ + c]);
            }
        }
        __syncthreads();

        float acc[4][4][4];
#pragma unroll
        for (int mi = 0; mi < 4; mi++)
#pragma unroll
            for (int nj = 0; nj < 4; nj++)
#pragma unroll
                for (int rr = 0; rr < 4; rr++) acc[mi][nj][rr] = 0.0f;

#pragma unroll
        for (int k8 = 0; k8 < 8; k8++) {
            unsigned a[4][4], b[4][2];
            int kk = k8 * 8 + t;
#pragma unroll
            for (int mi = 0; mi < 4; mi++) {
                int r = wm * 64 + mi * 16 + g;
                a[mi][0] = Qsm[r * STRQ + kk];
                a[mi][1] = Qsm[(r + 8) * STRQ + kk];
                a[mi][2] = Qsm[r * STRQ + kk + 4];
                a[mi][3] = Qsm[(r + 8) * STRQ + kk + 4];
            }
#pragma unroll
            for (int nj = 0; nj < 4; nj++) {
                int n = wn * 32 + nj * 8 + g;
                b[nj][0] = KVsm[n * STRK + kk];
                b[nj][1] = KVsm[n * STRK + kk + 4];
            }
#pragma unroll
            for (int mi = 0; mi < 4; mi++)
#pragma unroll
                for (int nj = 0; nj < 4; nj++)
                    mma_tf32(acc[mi][nj], a[mi], b[nj]);
        }

        // scale, write raw, per-warp row stats
#pragma unroll
        for (int mi = 0; mi < 4; mi++) {
#pragma unroll
            for (int nj = 0; nj < 4; nj++)
#pragma unroll
                for (int rr = 0; rr < 4; rr++) acc[mi][nj][rr] *= 0.125f;

            int rowl = wm * 64 + mi * 16 + g;
            int col0 = kt * 128 + wn * 32 + t * 2;
#pragma unroll
            for (int rr = 0; rr < 2; rr++) {
                int row = rowl + rr * 8;
#pragma unroll
                for (int nj = 0; nj < 4; nj++) {
                    float2 v = make_float2(acc[mi][nj][rr * 2], acc[mi][nj][rr * 2 + 1]);
                    *reinterpret_cast<float2*>(&Ab[(size_t)row * NK_ + col0 + nj * 8]) = v;
                }
                // warp-level row stats over 32 cols
                float mx = -1e30f;
#pragma unroll
                for (int nj = 0; nj < 4; nj++)
                    mx = fmaxf(mx, fmaxf(acc[mi][nj][rr * 2], acc[mi][nj][rr * 2 + 1]));
                mx = fmaxf(mx, __shfl_xor_sync(0xffffffffu, mx, 1));
                mx = fmaxf(mx, __shfl_xor_sync(0xffffffffu, mx, 2));
                float se = 0.0f;
#pragma unroll
                for (int nj = 0; nj < 4; nj++)
                    se += __expf(acc[mi][nj][rr * 2] - mx) +
                          __expf(acc[mi][nj][rr * 2 + 1] - mx);
                se += __shfl_xor_sync(0xffffffffu, se, 1);
                se += __shfl_xor_sync(0xffffffffu, se, 2);
                if (t == 0) {
                    redm[wn * 128 + row] = mx;
                    redl[wn * 128 + row] = se;
                }
            }
        }
        __syncthreads();
        if (tid < 128) {
            float m0 = redm[tid], m1 = redm[128 + tid];
            float m2 = redm[256 + tid], m3 = redm[384 + tid];
            float mt = fmaxf(fmaxf(m0, m1), fmaxf(m2, m3));
            float lt = redl[tid] * __expf(m0 - mt) + redl[128 + tid] * __expf(m1 - mt) +
                       redl[256 + tid] * __expf(m2 - mt) + redl[384 + tid] * __expf(m3 - mt);
            float mo = mrun[tid];
            float mn = fmaxf(mo, mt);
            lrun[tid] = lrun[tid] * __expf(mo - mn) + lt * __expf(mt - mn);
            mrun[tid] = mn;
        }
    }

    // prefetch V tile 0; finalize linv
#pragma unroll
    for (int it = 0; it < 8; it++) {
        int i = it * 256 + tid;
        int r = i >> 4, c = (i & 15) * 4;
        pre[it] = *reinterpret_cast<const float4*>(&Vg[(size_t)r * HD_ + c]);
    }
    if (tid < 128) lrun[tid] = 1.0f / lrun[tid];

    // ================= PASS 2 =================
    const int wm2 = w >> 1;  // 0..3
    const int wn2 = w & 1;   // 0..1
    float ctx[2][4][4];
#pragma unroll
    for (int mi = 0; mi < 2; mi++)
#pragma unroll
        for (int nj = 0; nj < 4; nj++)
#pragma unroll
            for (int rr = 0; rr < 4; rr++) ctx[mi][nj][rr] = 0.0f;

    for (int kt = 0; kt < 32; kt++) {
        __syncthreads();
        // STS V tile (stride 72)
#pragma unroll
        for (int it = 0; it < 8; it++) {
            int i = it * 256 + tid;
            int r = i >> 4, c = (i & 15) * 4;
            uint4 u = make_uint4(f2tf32(pre[it].x), f2tf32(pre[it].y),
                                 f2tf32(pre[it].z), f2tf32(pre[it].w));
            *reinterpret_cast<uint4*>(&KVsm[r * STRV + c]) = u;
        }
        if (kt + 1 < 32) {
            const float* Vt = Vg + (size_t)(kt + 1) * 128 * HD_;
#pragma unroll
            for (int it = 0; it < 8; it++) {
                int i = it * 256 + tid;
                int r = i >> 4, c = (i & 15) * 4;
                pre[it] = *reinterpret_cast<const float4*>(&Vt[(size_t)r * HD_ + c]);
            }
        }
        // normalize raw scores -> final A (gmem) + tf32 staging (smem)
#pragma unroll
        for (int it = 0; it < 16; it++) {
            int i = it * 256 + tid;           // 4096 float4 slots
            int r = i >> 5, c = (i & 31) * 4;
            float* p = &Ab[(size_t)r * NK_ + kt * 128 + c];
            float4 v = *reinterpret_cast<const float4*>(p);
            float m = mrun[r], li = lrun[r];
            v.x = __expf(v.x - m) * li;
            v.y = __expf(v.y - m) * li;
            v.z = __expf(v.z - m) * li;
            v.w = __expf(v.w - m) * li;
            *reinterpret_cast<float4*>(p) = v;
            uint4 u = make_uint4(f2tf32(v.x), f2tf32(v.y), f2tf32(v.z), f2tf32(v.w));
            *reinterpret_cast<uint4*>(&Asm[r * STRA + c]) = u;
        }
        __syncthreads();

        const unsigned* Au = (const unsigned*)Asm;
#pragma unroll
        for (int k8 = 0; k8 < 16; k8++) {
            unsigned a[2][4], b[4][2];
            int kk = k8 * 8 + t;
#pragma unroll
            for (int mi = 0; mi < 2; mi++) {
                int r = wm2 * 32 + mi * 16 + g;
                a[mi][0] = Au[r * STRA + kk];
                a[mi][1] = Au[(r + 8) * STRA + kk];
                a[mi][2] = Au[r * STRA + kk + 4];
                a[mi][3] = Au[(r + 8) * STRA + kk + 4];
            }
#pragma unroll
            for (int nj = 0; nj < 4; nj++) {
                int n = wn2 * 32 + nj * 8 + g;
                b[nj][0] = KVsm[kk * STRV + n];
                b[nj][1] = KVsm[(kk + 4) * STRV + n];
            }
#pragma unroll
            for (int mi = 0; mi < 2; mi++)
#pragma unroll
                for (int nj = 0; nj < 4; nj++)
                    mma_tf32(ctx[mi][nj], a[mi], b[nj]);
        }
    }

    // epilogue: ctx -> g_ctx[b][q][h*64+hd]
    const int b0 = bh >> 3;
    const int h  = bh & 7;
#pragma unroll
    for (int mi = 0; mi < 2; mi++) {
#pragma unroll
        for (int nj = 0; nj < 4; nj++) {
            int hd = wn2 * 32 + nj * 8 + t * 2;
#pragma unroll
            for (int rr = 0; rr < 2; rr++) {
                int q = qt * 128 + wm2 * 32 + mi * 16 + g + rr * 8;
                float2 v = make_float2(ctx[mi][nj][rr * 2], ctx[mi][nj][rr * 2 + 1]);
                *reinterpret_cast<float2*>(
                    &gctx[((size_t)b0 * NQ_ + q) * D_ + h * 64 + hd]) = v;
            }
        }
    }
}

// ---------------------------------------------------------------------------
extern "C" void kernel_launch(void* const* d_in, const int* in_sizes, int n_in,
                              void* d_out, int out_size)
{
    const float* q  = (const float*)d_in[0];
    const float* k  = (const float*)d_in[1];
    const float* v  = (const float*)d_in[2];
    const float* Wq = (const float*)d_in[3];
    const float* bq = (const float*)d_in[4];
    const float* Wk = (const float*)d_in[5];
    const float* bk = (const float*)d_in[6];
    const float* Wv = (const float*)d_in[7];
    const float* bv = (const float*)d_in[8];
    const float* Wo = (const float*)d_in[9];
    const float* bo = (const float*)d_in[10];

    float* out = (float*)d_out;                         // [B, NQ, D]
    float* A   = out + (size_t)B_ * NQ_ * D_;           // [B, H, NQ, NK]

    float *gQ, *gK, *gV, *gctx;
    cudaGetSymbolAddress((void**)&gQ,  g_Q);
    cudaGetSymbolAddress((void**)&gK,  g_K);
    cudaGetSymbolAddress((void**)&gV,  g_V);
    cudaGetSymbolAddress((void**)&gctx, g_ctx);

    cudaFuncSetAttribute(attn_tc, cudaFuncAttributeMaxDynamicSharedMemorySize,
                         SMEM_FLOATS * 4);

    dim3 blk(256);
    proj_tc<true><<<dim3(16, 4), blk>>>(q, Wq, bq, gQ, NQ_);     // Q proj  (M=2048)
    proj_tc<true><<<dim3(128, 4), blk>>>(k, Wk, bk, gK, NK_);    // K proj  (M=16384)
    proj_tc<true><<<dim3(128, 4), blk>>>(v, Wv, bv, gV, NK_);    // V proj
    attn_tc<<<128, blk, SMEM_FLOATS * 4>>>(gQ, gK, gV, A, gctx); // attention
    proj_tc<false><<<dim3(16, 4), blk>>>(gctx, Wo, bo, out, NQ_); // out proj
}

// round 3
// speedup vs baseline: 2.6380x; 1.2355x over previous
#include <cuda_runtime.h>
#include <math.h>

#define B_  4
#define H_  8
#define D_  512
#define HD_ 64
#define NQ_ 512
#define NK_ 4096

// exp(s/8) == exp2(s * 0.125 * log2(e))
#define EXPC 0.18033688011112042f

// ---------------- scratch (no-alloc rule) ----------------
__device__ float g_Q[(size_t)B_ * H_ * NQ_ * HD_];    // [B,H,NQ,HD]
__device__ float g_K[(size_t)B_ * H_ * NK_ * HD_];    // [B,H,NK,HD]
__device__ float g_V[(size_t)B_ * H_ * NK_ * HD_];    // [B,H,NK,HD]
__device__ float g_ctx[(size_t)B_ * NQ_ * D_];        // [B,NQ,D]

// ---------------- helpers ----------------
__device__ __forceinline__ unsigned f2tf32(float x) {
    unsigned r;
    asm("cvt.rna.tf32.f32 %0, %1;" : "=r"(r) : "f"(x));
    return r;
}

__device__ __forceinline__ void mma_tf32(float* d, const unsigned* a,
                                         const unsigned* b) {
    asm volatile(
        "mma.sync.aligned.m16n8k8.row.col.f32.tf32.tf32.f32 "
        "{%0,%1,%2,%3}, {%4,%5,%6,%7}, {%8,%9}, {%0,%1,%2,%3};"
        : "+f"(d[0]), "+f"(d[1]), "+f"(d[2]), "+f"(d[3])
        : "r"(a[0]), "r"(a[1]), "r"(a[2]), "r"(a[3]),
          "r"(b[0]), "r"(b[1]));
}

// ---------------------------------------------------------------------------
// TF32 projection GEMM: Y = X @ W^T + bias  (same as R2 — it performs OK)
// ---------------------------------------------------------------------------
template <bool SPLIT>
__global__ __launch_bounds__(256, 2) void proj_tc(
    const float* __restrict__ X, const float* __restrict__ W,
    const float* __restrict__ bias, float* __restrict__ Y, int N_seq)
{
    __shared__ unsigned Xs[128 * 36];
    __shared__ unsigned Ws[128 * 36];

    const int tid  = threadIdx.x;
    const int lane = tid & 31;
    const int w    = tid >> 5;
    const int wm   = w >> 2;
    const int wn   = w & 3;
    const int g    = lane >> 2;
    const int t    = lane & 3;
    const int bm   = blockIdx.x * 128;
    const int bn   = blockIdx.y * 128;

    float acc[4][4][4];
#pragma unroll
    for (int mi = 0; mi < 4; mi++)
#pragma unroll
        for (int nj = 0; nj < 4; nj++)
#pragma unroll
            for (int rr = 0; rr < 4; rr++) acc[mi][nj][rr] = 0.0f;

    for (int k0 = 0; k0 < D_; k0 += 32) {
        __syncthreads();
#pragma unroll
        for (int it = 0; it < 4; it++) {
            int i = it * 256 + tid;
            int r = i >> 3, c = (i & 7) * 4;
            float4 vx = *reinterpret_cast<const float4*>(
                &X[(size_t)(bm + r) * D_ + k0 + c]);
            uint4 ux = make_uint4(f2tf32(vx.x), f2tf32(vx.y), f2tf32(vx.z), f2tf32(vx.w));
            *reinterpret_cast<uint4*>(&Xs[r * 36 + c]) = ux;
            float4 vw = *reinterpret_cast<const float4*>(
                &W[(size_t)(bn + r) * D_ + k0 + c]);
            uint4 uw = make_uint4(f2tf32(vw.x), f2tf32(vw.y), f2tf32(vw.z), f2tf32(vw.w));
            *reinterpret_cast<uint4*>(&Ws[r * 36 + c]) = uw;
        }
        __syncthreads();

#pragma unroll
        for (int k8 = 0; k8 < 4; k8++) {
            unsigned a[4][4], b[4][2];
            int kk = k8 * 8 + t;
#pragma unroll
            for (int mi = 0; mi < 4; mi++) {
                int r = wm * 64 + mi * 16 + g;
                a[mi][0] = Xs[r * 36 + kk];
                a[mi][1] = Xs[(r + 8) * 36 + kk];
                a[mi][2] = Xs[r * 36 + kk + 4];
                a[mi][3] = Xs[(r + 8) * 36 + kk + 4];
            }
#pragma unroll
            for (int nj = 0; nj < 4; nj++) {
                int n = wn * 32 + nj * 8 + g;
                b[nj][0] = Ws[n * 36 + kk];
                b[nj][1] = Ws[n * 36 + kk + 4];
            }
#pragma unroll
            for (int mi = 0; mi < 4; mi++)
#pragma unroll
                for (int nj = 0; nj < 4; nj++)
                    mma_tf32(acc[mi][nj], a[mi], b[nj]);
        }
    }

#pragma unroll
    for (int mi = 0; mi < 4; mi++) {
#pragma unroll
        for (int nj = 0; nj < 4; nj++) {
            int n = bn + wn * 32 + nj * 8 + t * 2;
            float b0 = bias[n], b1 = bias[n + 1];
#pragma unroll
            for (int rr = 0; rr < 2; rr++) {
                int m = bm + wm * 64 + mi * 16 + g + rr * 8;
                float2 v = make_float2(acc[mi][nj][rr * 2] + b0,
                                       acc[mi][nj][rr * 2 + 1] + b1);
                if (SPLIT) {
                    int bb = m / N_seq;
                    int s  = m - bb * N_seq;
                    int h  = n >> 6;
                    int hd = n & 63;
                    *reinterpret_cast<float2*>(
                        &Y[((((size_t)bb * H_ + h) * N_seq + s) << 6) + hd]) = v;
                } else {
                    *reinterpret_cast<float2*>(&Y[(size_t)m * D_ + n]) = v;
                }
            }
        }
    }
}

// ---------------------------------------------------------------------------
// TF32 fused attention, max-free softmax, 3-phase, 2 CTAs/SM.
// CTA = (bh, qt): 64 q rows, ktile = 64. 256 threads, 8 warps.
//   Phase 1: S = Q K^T via mma; row sums of exp(S/8) (S discarded).
//   Phase 2: recompute S (K is L2-hot), A = exp(S/8)/l -> gmem once,
//            stage normalized P (tf32) in smem, ctx += P V via mma.
// ---------------------------------------------------------------------------
#define STRQ 68
#define STRK 68
#define STRV 72
#define STRP 68
#define OFQ 0
#define OFK 4352
#define OFV 8704
#define OFP 13312
#define OFL 17664
#define OFR 17728
#define ATT_SMEM_FLOATS 17984   // 71936 bytes

__global__ __launch_bounds__(256, 2) void attn_tc(
    const float* __restrict__ gQ, const float* __restrict__ gK,
    const float* __restrict__ gV, float* __restrict__ A_out,
    float* __restrict__ gctx)
{
    extern __shared__ float sm[];
    unsigned* Qs = (unsigned*)(sm + OFQ);
    unsigned* Ks = (unsigned*)(sm + OFK);
    unsigned* Vs = (unsigned*)(sm + OFV);
    unsigned* Ps = (unsigned*)(sm + OFP);
    float* linv  = sm + OFL;
    float* red   = sm + OFR;

    const int tid  = threadIdx.x;
    const int lane = tid & 31;
    const int w    = tid >> 5;
    const int g    = lane >> 2;
    const int t    = lane & 3;
    const int wm   = w >> 2;       // 0..1  (32 q rows)
    const int wn   = w & 3;        // 0..3  (16 cols)
    const int bh   = blockIdx.x >> 3;
    const int qt   = blockIdx.x & 7;

    const float* Qg = gQ + ((size_t)bh * NQ_ + qt * 64) * HD_;
    const float* Kg = gK + (size_t)bh * NK_ * HD_;
    const float* Vg = gV + (size_t)bh * NK_ * HD_;
    float* Ab = A_out + ((size_t)bh * NQ_ + qt * 64) * NK_;

    // load Q tile 64x64 (tf32 bits)
#pragma unroll
    for (int it = 0; it < 4; it++) {
        int i = it * 256 + tid;
        int r = i >> 4, c = (i & 15) * 4;
        float4 v = *reinterpret_cast<const float4*>(&Qg[(size_t)r * HD_ + c]);
        uint4 u = make_uint4(f2tf32(v.x), f2tf32(v.y), f2tf32(v.z), f2tf32(v.w));
        *reinterpret_cast<uint4*>(&Qs[r * STRQ + c]) = u;
    }

    float4 preK[4], preV[4];
    const int pr = tid >> 4, pc = (tid & 15) * 4;   // per-thread load slot base

    // ================= PHASE 1: row sums =================
    float psum[2][2];
    psum[0][0] = psum[0][1] = psum[1][0] = psum[1][1] = 0.0f;

#pragma unroll
    for (int it = 0; it < 4; it++)
        preK[it] = *reinterpret_cast<const float4*>(
            &Kg[(size_t)(it * 16 + pr) * HD_ + pc]);

    for (int kt = 0; kt < 64; kt++) {
        __syncthreads();
#pragma unroll
        for (int it = 0; it < 4; it++) {
            int r = it * 16 + pr;
            uint4 u = make_uint4(f2tf32(preK[it].x), f2tf32(preK[it].y),
                                 f2tf32(preK[it].z), f2tf32(preK[it].w));
            *reinterpret_cast<uint4*>(&Ks[r * STRK + pc]) = u;
        }
        if (kt + 1 < 64) {
            const float* Kt = Kg + (size_t)(kt + 1) * 64 * HD_;
#pragma unroll
            for (int it = 0; it < 4; it++)
                preK[it] = *reinterpret_cast<const float4*>(
                    &Kt[(size_t)(it * 16 + pr) * HD_ + pc]);
        }
        __syncthreads();

        float s[2][2][4];
#pragma unroll
        for (int mi = 0; mi < 2; mi++)
#pragma unroll
            for (int nj = 0; nj < 2; nj++)
#pragma unroll
                for (int rr = 0; rr < 4; rr++) s[mi][nj][rr] = 0.0f;

#pragma unroll
        for (int k8 = 0; k8 < 8; k8++) {
            unsigned a[2][4], b[2][2];
            int kk = k8 * 8 + t;
#pragma unroll
            for (int mi = 0; mi < 2; mi++) {
                int r = wm * 32 + mi * 16 + g;
                a[mi][0] = Qs[r * STRQ + kk];
                a[mi][1] = Qs[(r + 8) * STRQ + kk];
                a[mi][2] = Qs[r * STRQ + kk + 4];
                a[mi][3] = Qs[(r + 8) * STRQ + kk + 4];
            }
#pragma unroll
            for (int nj = 0; nj < 2; nj++) {
                int n = wn * 16 + nj * 8 + g;
                b[nj][0] = Ks[n * STRK + kk];
                b[nj][1] = Ks[n * STRK + kk + 4];
            }
#pragma unroll
            for (int mi = 0; mi < 2; mi++)
#pragma unroll
                for (int nj = 0; nj < 2; nj++)
                    mma_tf32(s[mi][nj], a[mi], b[nj]);
        }

#pragma unroll
        for (int mi = 0; mi < 2; mi++)
#pragma unroll
            for (int rr = 0; rr < 2; rr++)
                psum[mi][rr] += exp2f(s[mi][0][rr * 2] * EXPC) +
                                exp2f(s[mi][0][rr * 2 + 1] * EXPC) +
                                exp2f(s[mi][1][rr * 2] * EXPC) +
                                exp2f(s[mi][1][rr * 2 + 1] * EXPC);
    }

    // reduce row sums -> linv
#pragma unroll
    for (int mi = 0; mi < 2; mi++)
#pragma unroll
        for (int rr = 0; rr < 2; rr++) {
            float v = psum[mi][rr];
            v += __shfl_xor_sync(0xffffffffu, v, 1);
            v += __shfl_xor_sync(0xffffffffu, v, 2);
            if (t == 0) red[wn * 64 + wm * 32 + mi * 16 + g + rr * 8] = v;
        }
    __syncthreads();
    if (tid < 64)
        linv[tid] = 1.0f / (red[tid] + red[64 + tid] + red[128 + tid] + red[192 + tid]);
    __syncthreads();

    // per-thread 1/l for the rows this thread owns
    float li[2][2];
#pragma unroll
    for (int mi = 0; mi < 2; mi++)
#pragma unroll
        for (int rr = 0; rr < 2; rr++)
            li[mi][rr] = linv[wm * 32 + mi * 16 + g + rr * 8];

    // ================= PHASE 2: A + ctx =================
    float ctx[2][2][4];
#pragma unroll
    for (int mi = 0; mi < 2; mi++)
#pragma unroll
        for (int nj = 0; nj < 2; nj++)
#pragma unroll
            for (int rr = 0; rr < 4; rr++) ctx[mi][nj][rr] = 0.0f;

#pragma unroll
    for (int it = 0; it < 4; it++) {
        preK[it] = *reinterpret_cast<const float4*>(
            &Kg[(size_t)(it * 16 + pr) * HD_ + pc]);
        preV[it] = *reinterpret_cast<const float4*>(
            &Vg[(size_t)(it * 16 + pr) * HD_ + pc]);
    }

    for (int kt = 0; kt < 64; kt++) {
        __syncthreads();
#pragma unroll
        for (int it = 0; it < 4; it++) {
            int r = it * 16 + pr;
            uint4 uk = make_uint4(f2tf32(preK[it].x), f2tf32(preK[it].y),
                                  f2tf32(preK[it].z), f2tf32(preK[it].w));
            *reinterpret_cast<uint4*>(&Ks[r * STRK + pc]) = uk;
            uint4 uv = make_uint4(f2tf32(preV[it].x), f2tf32(preV[it].y),
                                  f2tf32(preV[it].z), f2tf32(preV[it].w));
            *reinterpret_cast<uint4*>(&Vs[r * STRV + pc]) = uv;
        }
        if (kt + 1 < 64) {
            const float* Kt = Kg + (size_t)(kt + 1) * 64 * HD_;
            const float* Vt = Vg + (size_t)(kt + 1) * 64 * HD_;
#pragma unroll
            for (int it = 0; it < 4; it++) {
                preK[it] = *reinterpret_cast<const float4*>(
                    &Kt[(size_t)(it * 16 + pr) * HD_ + pc]);
                preV[it] = *reinterpret_cast<const float4*>(
                    &Vt[(size_t)(it * 16 + pr) * HD_ + pc]);
            }
        }
        __syncthreads();

        float s[2][2][4];
#pragma unroll
        for (int mi = 0; mi < 2; mi++)
#pragma unroll
            for (int nj = 0; nj < 2; nj++)
#pragma unroll
                for (int rr = 0; rr < 4; rr++) s[mi][nj][rr] = 0.0f;

#pragma unroll
        for (int k8 = 0; k8 < 8; k8++) {
            unsigned a[2][4], b[2][2];
            int kk = k8 * 8 + t;
#pragma unroll
            for (int mi = 0; mi < 2; mi++) {
                int r = wm * 32 + mi * 16 + g;
                a[mi][0] = Qs[r * STRQ + kk];
                a[mi][1] = Qs[(r + 8) * STRQ + kk];
                a[mi][2] = Qs[r * STRQ + kk + 4];
                a[mi][3] = Qs[(r + 8) * STRQ + kk + 4];
            }
#pragma unroll
            for (int nj = 0; nj < 2; nj++) {
                int n = wn * 16 + nj * 8 + g;
                b[nj][0] = Ks[n * STRK + kk];
                b[nj][1] = Ks[n * STRK + kk + 4];
            }
#pragma unroll
            for (int mi = 0; mi < 2; mi++)
#pragma unroll
                for (int nj = 0; nj < 2; nj++)
                    mma_tf32(s[mi][nj], a[mi], b[nj]);
        }

        // normalize, write final A, stage P
#pragma unroll
        for (int mi = 0; mi < 2; mi++) {
#pragma unroll
            for (int rr = 0; rr < 2; rr++) {
                int row = wm * 32 + mi * 16 + g + rr * 8;
                float l = li[mi][rr];
#pragma unroll
                for (int nj = 0; nj < 2; nj++) {
                    float p0 = exp2f(s[mi][nj][rr * 2] * EXPC) * l;
                    float p1 = exp2f(s[mi][nj][rr * 2 + 1] * EXPC) * l;
                    int col = wn * 16 + nj * 8 + t * 2;
                    *reinterpret_cast<float2*>(
                        &Ab[(size_t)row * NK_ + kt * 64 + col]) = make_float2(p0, p1);
                    Ps[row * STRP + col] = f2tf32(p0);
                    Ps[row * STRP + col + 1] = f2tf32(p1);
                }
            }
        }
        __syncthreads();

        // ctx += P V
#pragma unroll
        for (int k8 = 0; k8 < 8; k8++) {
            unsigned a[2][4], b[2][2];
            int kk = k8 * 8 + t;
#pragma unroll
            for (int mi = 0; mi < 2; mi++) {
                int r = wm * 32 + mi * 16 + g;
                a[mi][0] = Ps[r * STRP + kk];
                a[mi][1] = Ps[(r + 8) * STRP + kk];
                a[mi][2] = Ps[r * STRP + kk + 4];
                a[mi][3] = Ps[(r + 8) * STRP + kk + 4];
            }
#pragma unroll
            for (int nj = 0; nj < 2; nj++) {
                int n = wn * 16 + nj * 8 + g;
                b[nj][0] = Vs[kk * STRV + n];
                b[nj][1] = Vs[(kk + 4) * STRV + n];
            }
#pragma unroll
            for (int mi = 0; mi < 2; mi++)
#pragma unroll
                for (int nj = 0; nj < 2; nj++)
                    mma_tf32(ctx[mi][nj], a[mi], b[nj]);
        }
    }

    // epilogue: ctx -> g_ctx[b][q][h*64+hd]
    const int b0 = bh >> 3;
    const int h  = bh & 7;
#pragma unroll
    for (int mi = 0; mi < 2; mi++) {
#pragma unroll
        for (int nj = 0; nj < 2; nj++) {
            int hd = wn * 16 + nj * 8 + t * 2;
#pragma unroll
            for (int rr = 0; rr < 2; rr++) {
                int q = qt * 64 + wm * 32 + mi * 16 + g + rr * 8;
                float2 v = make_float2(ctx[mi][nj][rr * 2], ctx[mi][nj][rr * 2 + 1]);
                *reinterpret_cast<float2*>(
                    &gctx[((size_t)b0 * NQ_ + q) * D_ + h * 64 + hd]) = v;
            }
        }
    }
}

// ---------------------------------------------------------------------------
extern "C" void kernel_launch(void* const* d_in, const int* in_sizes, int n_in,
                              void* d_out, int out_size)
{
    const float* q  = (const float*)d_in[0];
    const float* k  = (const float*)d_in[1];
    const float* v  = (const float*)d_in[2];
    const float* Wq = (const float*)d_in[3];
    const float* bq = (const float*)d_in[4];
    const float* Wk = (const float*)d_in[5];
    const float* bk = (const float*)d_in[6];
    const float* Wv = (const float*)d_in[7];
    const float* bv = (const float*)d_in[8];
    const float* Wo = (const float*)d_in[9];
    const float* bo = (const float*)d_in[10];

    float* out = (float*)d_out;                         // [B, NQ, D]
    float* A   = out + (size_t)B_ * NQ_ * D_;           // [B, H, NQ, NK]

    float *gQ, *gK, *gV, *gctx;
    cudaGetSymbolAddress((void**)&gQ,  g_Q);
    cudaGetSymbolAddress((void**)&gK,  g_K);
    cudaGetSymbolAddress((void**)&gV,  g_V);
    cudaGetSymbolAddress((void**)&gctx, g_ctx);

    cudaFuncSetAttribute(attn_tc, cudaFuncAttributeMaxDynamicSharedMemorySize,
                         ATT_SMEM_FLOATS * 4);

    dim3 blk(256);
    proj_tc<true><<<dim3(16, 4), blk>>>(q, Wq, bq, gQ, NQ_);
    proj_tc<true><<<dim3(128, 4), blk>>>(k, Wk, bk, gK, NK_);
    proj_tc<true><<<dim3(128, 4), blk>>>(v, Wv, bv, gV, NK_);
    attn_tc<<<256, blk, ATT_SMEM_FLOATS * 4>>>(gQ, gK, gV, A, gctx);
    proj_tc<false><<<dim3(16, 4), blk>>>(gctx, Wo, bo, out, NQ_);
}